// round 10
// baseline (speedup 1.0000x reference)
#include <cuda_runtime.h>
#include <math.h>

// Shape fixed by reference: [4,1,128,256,256] fp32
#define IMG_W    256
#define IMG_H    256
#define NSLICES  512                  // B*D
#define STRIP_H  64                   // rows per block
#define STRIPS   (IMG_H / STRIP_H)    // 4
#define NB       (NSLICES * STRIPS)   // 2048 blocks
#define YT       4                    // y groups per block (256 thr = 64 x * 4 y)
#define NR       (STRIP_H / YT)       // 16 output rows per thread
#define N_TOTAL  (4.0 * 128.0 * 256.0 * 256.0)

__device__ float        g_partials[NB];
__device__ unsigned int g_count = 0;

typedef unsigned long long u64;

// Packed constants: {lo, hi} identical
#define TWO2  0x4000000040000000ULL   // {2.0f, 2.0f}
#define NEG2  0xBF800000BF800000ULL   // {-1.0f, -1.0f}
#define EPS2  0x322BCC77322BCC77ULL   // {1e-8f, 1e-8f}

__device__ __forceinline__ u64 pack2(float lo, float hi) {
    u64 d; asm("mov.b64 %0, {%1, %2};" : "=l"(d) : "f"(lo), "f"(hi)); return d;
}
__device__ __forceinline__ void unpack2(u64 d, float& lo, float& hi) {
    asm("mov.b64 {%0, %1}, %2;" : "=f"(lo), "=f"(hi) : "l"(d));
}
__device__ __forceinline__ u64 add2(u64 a, u64 b) {
    u64 d; asm("add.rn.f32x2 %0, %1, %2;" : "=l"(d) : "l"(a), "l"(b)); return d;
}
__device__ __forceinline__ u64 fma2(u64 a, u64 b, u64 c) {
    u64 d; asm("fma.rn.f32x2 %0, %1, %2, %3;" : "=l"(d) : "l"(a), "l"(b), "l"(c)); return d;
}
__device__ __forceinline__ float sqrt_approx(float x) {
    float r; asm("sqrt.approx.f32 %0, %1;" : "=f"(r) : "f"(x)); return r;
}

struct Row6 { float n0, n1, n2, n3, n4, n5; };  // l, v0..v3, r

// Raw loads only: one aligned float4 + two independent halo scalars
// (L1 hits — same 128B lines as neighboring lanes' vectors).
// No shuffles, no convergence points; all LDGs independent -> high MLP.
__device__ __forceinline__ Row6 load_row(const float* __restrict__ p,
                                         bool row_ok, bool has_l, bool has_r)
{
    Row6 o;
    float4 v = make_float4(0.f, 0.f, 0.f, 0.f);
    float  l = 0.f, r = 0.f;
    if (row_ok) {
        v = *reinterpret_cast<const float4*>(p);
        if (has_l) l = p[-1];
        if (has_r) r = p[4];
    }
    o.n0 = l; o.n1 = v.x; o.n2 = v.y; o.n3 = v.z; o.n4 = v.w; o.n5 = r;
    return o;
}

// Packed separable row aggregates: two f32x2 pairs cover 4 columns.
//   h1 = n[j+2] - n[j]            (ex = h1[y-1] + 2h1[y] + h1[y+1])
//   h2 = n[j] + 2n[j+1] + n[j+2]  (ey = h2[y+1] - h2[y-1])
// Pairs {v0,v1},{v2,v3} come free from the float4; only L/M/R are packed.
struct Agg { u64 h1a, h1b, h2a, h2b; };

__device__ __forceinline__ Agg agg_row(const Row6& n)
{
    const u64 A = pack2(n.n1, n.n2);   // {v0, v1}  (adjacent regs: ~free)
    const u64 B = pack2(n.n3, n.n4);   // {v2, v3}
    const u64 L = pack2(n.n0, n.n1);   // {l , v0}
    const u64 M = pack2(n.n2, n.n3);   // {v1, v2}
    const u64 R = pack2(n.n4, n.n5);   // {v3, r }
    Agg a;
    a.h1a = fma2(L, NEG2, M);                    // {v1-l,  v2-v0}
    a.h1b = fma2(M, NEG2, R);                    // {v3-v1, r -v2}
    a.h2a = fma2(TWO2, A, add2(L, M));           // cols 0,1
    a.h2b = fma2(TWO2, B, add2(M, R));           // cols 2,3
    return a;
}

__global__ __launch_bounds__(256, 4)
void edge_loss_kernel(const float* __restrict__ pred,
                      const float* __restrict__ target,
                      float* __restrict__ out)
{
    __shared__ float warp_sums[8];
    __shared__ int   s_last;

    const int tid  = threadIdx.x;
    const int x    = tid & 63;            // 0..63 -> cols [4x, 4x+3]
    const int ty   = tid >> 6;            // 0..3
    const int lane = tid & 31;
    const int cb   = x << 2;
    const bool has_l = (x != 0);
    const bool has_r = (x != 63);

    const int r0 = blockIdx.x * STRIP_H + ty * NR;

    const size_t base = (size_t)blockIdx.y * (IMG_H * IMG_W);
    const float* __restrict__ P = pred + base + cb;
    const float* __restrict__ T = target + base + cb;

    Agg pp, pc, tp, tc;   // rolling packed aggregates: prev / cur rows

    // Prologue: rows r0-1 (prev) and r0 (cur)
    {
        const Row6 a = load_row(P + (r0 - 1) * IMG_W, r0 > 0, has_l, has_r);
        const Row6 b = load_row(T + (r0 - 1) * IMG_W, r0 > 0, has_l, has_r);
        const Row6 c = load_row(P + r0 * IMG_W, true, has_l, has_r);
        const Row6 d = load_row(T + r0 * IMG_W, true, has_l, has_r);
        pp = agg_row(a); tp = agg_row(b);
        pc = agg_row(c); tc = agg_row(d);
    }

    // Prefetch first body row (r0+1)
    const float* pRow = P + (r0 + 1) * IMG_W;
    const float* tRow = T + (r0 + 1) * IMG_W;
    Row6 pcur = load_row(pRow, r0 + 1 < IMG_H, has_l, has_r);
    Row6 tcur = load_row(tRow, r0 + 1 < IMG_H, has_l, has_r);

    float acc = 0.f;

    #pragma unroll
    for (int i = 0; i < NR; i++) {
        // Prefetch row r0+2+i while computing on (pcur, tcur)
        const bool nok = (r0 + 2 + i < IMG_H);
        pRow += IMG_W; tRow += IMG_W;
        const Row6 pnxt = load_row(pRow, nok, has_l, has_r);
        const Row6 tnxt = load_row(tRow, nok, has_l, has_r);

        const Agg pn = agg_row(pcur);
        const Agg tn = agg_row(tcur);

        // Packed vertical combines (2 cols per op)
        const u64 pexa = add2(fma2(TWO2, pc.h1a, pp.h1a), pn.h1a);
        const u64 pexb = add2(fma2(TWO2, pc.h1b, pp.h1b), pn.h1b);
        const u64 peya = fma2(pp.h2a, NEG2, pn.h2a);
        const u64 peyb = fma2(pp.h2b, NEG2, pn.h2b);
        const u64 psa  = fma2(pexa, pexa, fma2(peya, peya, EPS2));
        const u64 psb  = fma2(pexb, pexb, fma2(peyb, peyb, EPS2));

        const u64 texa = add2(fma2(TWO2, tc.h1a, tp.h1a), tn.h1a);
        const u64 texb = add2(fma2(TWO2, tc.h1b, tp.h1b), tn.h1b);
        const u64 teya = fma2(tp.h2a, NEG2, tn.h2a);
        const u64 teyb = fma2(tp.h2b, NEG2, tn.h2b);
        const u64 tsa  = fma2(texa, texa, fma2(teya, teya, EPS2));
        const u64 tsb  = fma2(texb, texb, fma2(teyb, teyb, EPS2));

        float p0, p1, p2, p3, t0, t1, t2, t3;
        unpack2(psa, p0, p1); unpack2(psb, p2, p3);
        unpack2(tsa, t0, t1); unpack2(tsb, t2, t3);

        acc += fabsf(sqrt_approx(p0) - sqrt_approx(t0));
        acc += fabsf(sqrt_approx(p1) - sqrt_approx(t1));
        acc += fabsf(sqrt_approx(p2) - sqrt_approx(t2));
        acc += fabsf(sqrt_approx(p3) - sqrt_approx(t3));

        pp = pc; pc = pn;
        tp = tc; tc = tn;
        pcur = pnxt; tcur = tnxt;
    }

    // ---- Deterministic block reduction ----
    #pragma unroll
    for (int off = 16; off > 0; off >>= 1)
        acc += __shfl_down_sync(0xffffffffu, acc, off);
    if (lane == 0) warp_sums[tid >> 5] = acc;
    __syncthreads();

    if (tid == 0) {
        float s = 0.f;
        #pragma unroll
        for (int i = 0; i < 8; i++) s += warp_sums[i];
        g_partials[blockIdx.y * gridDim.x + blockIdx.x] = s;
        __threadfence();
        const unsigned old = atomicAdd(&g_count, 1u);
        s_last = (old == NB - 1) ? 1 : 0;
    }
    __syncthreads();

    // ---- Last block: deterministic final reduce (fixed order, double) ----
    if (s_last) {
        __shared__ double dred[256];
        double s = 0.0;
        #pragma unroll 8
        for (int i = tid; i < NB; i += 256)
            s += (double)g_partials[i];
        dred[tid] = s;
        __syncthreads();
        #pragma unroll
        for (int off = 128; off > 0; off >>= 1) {
            if (tid < off) dred[tid] += dred[tid + off];
            __syncthreads();
        }
        if (tid == 0) {
            out[0]  = (float)(dred[0] / N_TOTAL);
            g_count = 0;   // reset for next graph replay
        }
    }
}

extern "C" void kernel_launch(void* const* d_in, const int* in_sizes, int n_in,
                              void* d_out, int out_size)
{
    (void)in_sizes; (void)n_in; (void)out_size;
    const float* pred   = (const float*)d_in[0];
    const float* target = (const float*)d_in[1];
    float* out = (float*)d_out;

    dim3 grid(STRIPS, NSLICES);   // 4 x 512 = 2048 blocks
    edge_loss_kernel<<<grid, 256>>>(pred, target, out);
}

// round 11
// speedup vs baseline: 1.2778x; 1.2778x over previous
#include <cuda_runtime.h>
#include <math.h>

// Shape fixed by reference: [4,1,128,256,256] fp32
#define IMG_W    256
#define IMG_H    256
#define NSLICES  512                  // B*D
#define STRIP_H  32                   // rows per block
#define STRIPS   (IMG_H / STRIP_H)    // 8
#define NB       (NSLICES * STRIPS)   // 4096 blocks
#define YT       2                    // y groups per block (256 thr = 128 x * 2 y)
#define NR       (STRIP_H / YT)       // 16 output rows per thread
#define N_TOTAL  (4.0 * 128.0 * 256.0 * 256.0)
#define ROW_BYTES (IMG_W * 4)

__device__ float        g_partials[NB];
__device__ unsigned int g_count = 0;

__device__ __forceinline__ float sqrt_approx(float x) {
    float r; asm("sqrt.approx.f32 %0, %1;" : "=f"(r) : "f"(x)); return r;
}

struct Row4 { float n0, n1, n2, n3; };   // cols [cb-1, cb, cb+1, cb+2]

// Raw loads only: one aligned float2 + two independent halo scalars
// (L1 hits — same 128B lines as neighboring lanes' vectors).
// No shuffles, no convergence points; all LDGs independent.
__device__ __forceinline__ Row4 load_row2(const float* __restrict__ base,
                                          int byte_off,
                                          bool row_ok, bool has_l, bool has_r)
{
    const float* p = (const float*)((const char*)base + byte_off);
    Row4 o;
    float2 v = make_float2(0.f, 0.f);
    float  l = 0.f, r = 0.f;
    if (row_ok) {
        v = *reinterpret_cast<const float2*>(p);
        if (has_l) l = p[-1];
        if (has_r) r = p[2];
    }
    o.n0 = l; o.n1 = v.x; o.n2 = v.y; o.n3 = r;
    return o;
}

// Separable row aggregates for 2 columns:
//   h1 = r - l        (ex = h1[y-1] + 2h1[y] + h1[y+1])
//   h2 = l + 2m + r   (ey = h2[y+1] - h2[y-1])
__device__ __forceinline__ void row_agg2(const Row4& n, float h1[2], float h2[2])
{
    h1[0] = n.n2 - n.n0;  h2[0] = fmaf(2.f, n.n1, n.n0 + n.n2);
    h1[1] = n.n3 - n.n1;  h2[1] = fmaf(2.f, n.n2, n.n1 + n.n3);
}

__global__ __launch_bounds__(256, 6)
void edge_loss_kernel(const float* __restrict__ pred,
                      const float* __restrict__ target,
                      float* __restrict__ out)
{
    __shared__ float warp_sums[8];
    __shared__ int   s_last;

    const int tid  = threadIdx.x;
    const int xt   = tid & 127;           // 0..127 -> cols [2xt, 2xt+1]
    const int ty   = tid >> 7;            // 0..1
    const int lane = tid & 31;
    const int cb   = xt << 1;
    const bool has_l = (xt != 0);
    const bool has_r = (xt != 127);

    const int r0 = blockIdx.x * STRIP_H + ty * NR;

    const size_t base = (size_t)blockIdx.y * (IMG_H * IMG_W);
    const float* __restrict__ P = pred + base + cb + (size_t)r0 * IMG_W;
    const float* __restrict__ T = target + base + cb + (size_t)r0 * IMG_W;

    float ph1p[2], ph2p[2], ph1c[2], ph2c[2];
    float th1p[2], th2p[2], th1c[2], th2c[2];

    // Prologue: rows r0-1 (off=-ROW_BYTES) and r0 (off=0)
    {
        const Row4 pp = load_row2(P, -ROW_BYTES, r0 > 0, has_l, has_r);
        const Row4 tp = load_row2(T, -ROW_BYTES, r0 > 0, has_l, has_r);
        const Row4 pc = load_row2(P, 0, true, has_l, has_r);
        const Row4 tc = load_row2(T, 0, true, has_l, has_r);
        row_agg2(pp, ph1p, ph2p);
        row_agg2(tp, th1p, th2p);
        row_agg2(pc, ph1c, ph2c);
        row_agg2(tc, th1c, th2c);
    }

    // Prefetch first body row (r0+1); off tracks the *prefetched* row
    int off = ROW_BYTES;
    Row4 pcur = load_row2(P, off, r0 + 1 < IMG_H, has_l, has_r);
    Row4 tcur = load_row2(T, off, r0 + 1 < IMG_H, has_l, has_r);

    float acc = 0.f;

    #pragma unroll
    for (int i = 0; i < NR; i++) {
        // Prefetch row r0+2+i while computing on (pcur, tcur)
        const bool nok = (r0 + 2 + i < IMG_H);
        off += ROW_BYTES;
        const Row4 pnxt = load_row2(P, off, nok, has_l, has_r);
        const Row4 tnxt = load_row2(T, off, nok, has_l, has_r);

        float ph1n[2], ph2n[2], th1n[2], th2n[2];
        row_agg2(pcur, ph1n, ph2n);
        row_agg2(tcur, th1n, th2n);

        #pragma unroll
        for (int j = 0; j < 2; j++) {
            float ex = fmaf(2.f, ph1c[j], ph1p[j]) + ph1n[j];
            float ey = ph2n[j] - ph2p[j];
            const float magp = sqrt_approx(fmaf(ex, ex, fmaf(ey, ey, 1e-8f)));

            ex = fmaf(2.f, th1c[j], th1p[j]) + th1n[j];
            ey = th2n[j] - th2p[j];
            const float magt = sqrt_approx(fmaf(ex, ex, fmaf(ey, ey, 1e-8f)));

            acc += fabsf(magp - magt);
        }

        #pragma unroll
        for (int j = 0; j < 2; j++) {
            ph1p[j] = ph1c[j]; ph1c[j] = ph1n[j];
            ph2p[j] = ph2c[j]; ph2c[j] = ph2n[j];
            th1p[j] = th1c[j]; th1c[j] = th1n[j];
            th2p[j] = th2c[j]; th2c[j] = th2n[j];
        }
        pcur = pnxt; tcur = tnxt;
    }

    // ---- Deterministic block reduction ----
    #pragma unroll
    for (int offr = 16; offr > 0; offr >>= 1)
        acc += __shfl_down_sync(0xffffffffu, acc, offr);
    if (lane == 0) warp_sums[tid >> 5] = acc;
    __syncthreads();

    if (tid == 0) {
        float s = 0.f;
        #pragma unroll
        for (int i = 0; i < 8; i++) s += warp_sums[i];
        g_partials[blockIdx.y * gridDim.x + blockIdx.x] = s;
        __threadfence();
        const unsigned old = atomicAdd(&g_count, 1u);
        s_last = (old == NB - 1) ? 1 : 0;
    }
    __syncthreads();

    // ---- Last block: deterministic final reduce (fixed order, double) ----
    if (s_last) {
        __shared__ double dred[256];
        double s = 0.0;
        #pragma unroll 8
        for (int i = tid; i < NB; i += 256)
            s += (double)g_partials[i];
        dred[tid] = s;
        __syncthreads();
        #pragma unroll
        for (int offr = 128; offr > 0; offr >>= 1) {
            if (tid < offr) dred[tid] += dred[tid + offr];
            __syncthreads();
        }
        if (tid == 0) {
            out[0]  = (float)(dred[0] / N_TOTAL);
            g_count = 0;   // reset for next graph replay
        }
    }
}

extern "C" void kernel_launch(void* const* d_in, const int* in_sizes, int n_in,
                              void* d_out, int out_size)
{
    (void)in_sizes; (void)n_in; (void)out_size;
    const float* pred   = (const float*)d_in[0];
    const float* target = (const float*)d_in[1];
    float* out = (float*)d_out;

    dim3 grid(STRIPS, NSLICES);   // 8 x 512 = 4096 blocks
    edge_loss_kernel<<<grid, 256>>>(pred, target, out);
}